// round 12
// baseline (speedup 1.0000x reference)
#include <cuda_runtime.h>
#include <math.h>

#define Bsz 2048
#define Lsz 64
#define Esz 128
#define Hsz 128
#define NSTEPS 126
#define BM 7
#define NT 512
#define GRID 293               // ceil(2048/7)
#define NEGV -1000000000.0f

// scratch (module-static device arrays: allowed)
__device__ float d_eg[(size_t)Bsz * Lsz * Hsz];   // e_g[b][l][h]
__device__ float d_ep[(size_t)Bsz * Lsz * Hsz];   // e_p[b][l][h]
__device__ float4 d_wt4[64 * 512];                // transposed LSTM weights [k4][o] (Wih 0..31, Whh 32..63)
__device__ float4 d_wq4[2 * 32 * 128];            // transposed gWq|pWq [which][k4][o]
__device__ float  d_P[(size_t)Bsz * Lsz * 512];   // P[b][l][o] = Wih·emb[l,b] + bt
__device__ float  d_P0[(size_t)Bsz * 512];        // P0[b][o]   = Wih·dec[b] + bt

// packed f32x2 FMA (Blackwell): d = a*b + c elementwise, IEEE rn per lane
#define FMA2(d, a, b, c) \
    asm("fma.rn.f32x2 %0, %1, %2, %3;" : "=l"(d) : "l"(a), "l"(b), "l"(c))

__device__ __forceinline__ unsigned long long pack2(float lo, float hi) {
    unsigned long long r;
    asm("mov.b64 %0, {%1, %2};" : "=l"(r) : "f"(lo), "f"(hi));
    return r;
}
__device__ __forceinline__ float hsum2(unsigned long long v) {
    float a, b;
    asm("mov.b64 {%0, %1}, %2;" : "=f"(a), "=f"(b) : "l"(v));
    return a + b;
}

__device__ __forceinline__ float ftanh(float x) {
    float e = __expf(2.f * x);
    return 1.f - __fdividef(2.f, e + 1.f);
}
__device__ __forceinline__ float fsigm(float x) {
    return __fdividef(1.f, 1.f + __expf(-x));
}

// ---------------------------------------------------------------------------
// Transpose LSTM weights + Wq matrices into coalesced [k][o] layouts
// ---------------------------------------------------------------------------
__global__ void __launch_bounds__(512) ptrnet_prew(
    const float* __restrict__ Wih, const float* __restrict__ Whh,
    const float* __restrict__ gWq, const float* __restrict__ pWq)
{
    int i = blockIdx.x * blockDim.x + threadIdx.x;
    if (i < 64 * 512) {
        int k4 = i >> 9, o = i & 511;
        const float* src = (k4 < 32) ? (Wih + o * 128 + (k4 << 2))
                                     : (Whh + o * 128 + ((k4 - 32) << 2));
        d_wt4[i] = *reinterpret_cast<const float4*>(src);
    } else if (i < 64 * 512 + 2 * 4096) {
        int j = i - 64 * 512;
        int which = j >> 12, r = j & 4095;
        int k4 = r >> 7, o = r & 127;
        const float* W = which ? pWq : gWq;
        d_wq4[which * 4096 + k4 * 128 + o] =
            *reinterpret_cast<const float4*>(W + o * 128 + (k4 << 2));
    }
}

// ---------------------------------------------------------------------------
// Precompute P[b][l][o] = Wih·emb[l][b] + (bih+bhh)[o]  and P0 from decoder.
// ---------------------------------------------------------------------------
__global__ void __launch_bounds__(512) ptrnet_preP(
    const float* __restrict__ emb, const float* __restrict__ dec,
    const float* __restrict__ bih, const float* __restrict__ bhh)
{
    __shared__ float xs[Lsz * Esz];   // 32KB
    __shared__ float ds[Esz];
    const int b = blockIdx.x, o = threadIdx.x;

    for (int idx = o; idx < Lsz * Esz; idx += 512) {
        int l = idx >> 7, e = idx & 127;
        xs[idx] = emb[((size_t)l * Bsz + b) * Esz + e];
    }
    if (o < Esz) ds[o] = dec[(size_t)b * Esz + o];
    __syncthreads();

    const float bt = bih[o] + bhh[o];

    {   // P0
        unsigned long long acc = pack2(bt, 0.f);
        #pragma unroll 8
        for (int kk = 0; kk < 32; kk++) {
            ulonglong2 w2 = *reinterpret_cast<const ulonglong2*>(&d_wt4[(kk << 9) + o]);
            ulonglong2 x2 = *reinterpret_cast<const ulonglong2*>(&ds[kk << 2]);
            FMA2(acc, w2.x, x2.x, acc);
            FMA2(acc, w2.y, x2.y, acc);
        }
        d_P0[(size_t)b * 512 + o] = hsum2(acc);
    }
    for (int c = 0; c < 4; c++) {
        unsigned long long acc[16];
        #pragma unroll
        for (int j = 0; j < 16; j++) acc[j] = pack2(bt, 0.f);
        #pragma unroll 2
        for (int kk = 0; kk < 32; kk++) {
            ulonglong2 w2 = *reinterpret_cast<const ulonglong2*>(&d_wt4[(kk << 9) + o]);
            #pragma unroll
            for (int j = 0; j < 16; j++) {
                ulonglong2 x2 = *reinterpret_cast<const ulonglong2*>(
                    &xs[(((c << 4) + j) << 7) + (kk << 2)]);
                FMA2(acc[j], w2.x, x2.x, acc[j]);
                FMA2(acc[j], w2.y, x2.y, acc[j]);
            }
        }
        #pragma unroll
        for (int j = 0; j < 16; j++)
            d_P[(((size_t)b << 6) + (c << 4) + j) * 512 + o] = hsum2(acc[j]);
    }
}

// ---------------------------------------------------------------------------
// Precompute e_g/e_p
// ---------------------------------------------------------------------------
__global__ void __launch_bounds__(128) ptrnet_pre(
    const float* __restrict__ ctx,
    const float* __restrict__ gWref, const float* __restrict__ gbref,
    const float* __restrict__ pWref, const float* __restrict__ pbref)
{
    __shared__ float cs[Lsz * Hsz];
    const int b = blockIdx.x, t = threadIdx.x;
    for (int l = 0; l < Lsz; l++)
        cs[l * Hsz + t] = ctx[((size_t)l * Bsz + b) * Hsz + t];
    __syncthreads();

    {
        float acc[Lsz];
        #pragma unroll
        for (int l = 0; l < Lsz; l++) acc[l] = 0.f;
        const float4* wr = reinterpret_cast<const float4*>(gWref + t * Hsz);
        #pragma unroll 1
        for (int k4 = 0; k4 < 32; k4++) {
            float4 w = wr[k4];
            #pragma unroll
            for (int l = 0; l < Lsz; l++) {
                float4 c = *reinterpret_cast<const float4*>(&cs[l * Hsz + k4 * 4]);
                acc[l] += w.x * c.x + w.y * c.y + w.z * c.z + w.w * c.w;
            }
        }
        float bias = gbref[t];
        #pragma unroll
        for (int l = 0; l < Lsz; l++)
            d_eg[((size_t)b * Lsz + l) * Hsz + t] = acc[l] + bias;
    }
    {
        float acc[Lsz];
        #pragma unroll
        for (int l = 0; l < Lsz; l++) acc[l] = 0.f;
        const float4* wr = reinterpret_cast<const float4*>(pWref + t * Hsz);
        #pragma unroll 1
        for (int k4 = 0; k4 < 32; k4++) {
            float4 w = wr[k4];
            #pragma unroll
            for (int l = 0; l < Lsz; l++) {
                float4 c = *reinterpret_cast<const float4*>(&cs[l * Hsz + k4 * 4]);
                acc[l] += w.x * c.x + w.y * c.y + w.z * c.z + w.w * c.w;
            }
        }
        float bias = pbref[t];
        #pragma unroll
        for (int l = 0; l < Lsz; l++)
            d_ep[((size_t)b * Lsz + l) * Hsz + t] = acc[l] + bias;
    }
}

// ---------------------------------------------------------------------------
// Persistent decode kernel — 512 threads, BM=7, 2 CTAs/SM.
// Phase A: thread (mh, o2) computes outputs {o2, o2+256} over its m-subset,
// halving broadcast LDS traffic (dot-product order bitwise identical).
// smem float offsets:
// ---------------------------------------------------------------------------
#define OXH  0                     // [7][128] h                  896
#define OG   896                   // [7][512] gates / [28][128] qg-qp partials
#define OC   4480                  // [7][128]                    896
#define OQ   5376                  // [7][128]                    896
#define OGL  6272                  // [7][128]                    896
#define OU   7168                  // [7][64]                     448
#define OS   7616                  // [7][64]                     448
#define OGBQ 8064
#define OPBQ 8192
#define OGV  8320
#define OPV  8448
#define SMEM_FLOATS 8576           // 34304 bytes -> 2 CTAs/SM

__global__ void __launch_bounds__(NT, 2) ptrnet_main(
    const float* __restrict__ h0,  const float* __restrict__ c0,
    const float* __restrict__ gbq, const float* __restrict__ pbq,
    const float* __restrict__ gv,  const float* __restrict__ pv,
    float* __restrict__ out)
{
    extern __shared__ float s[];
    __shared__ unsigned long long mask_s[BM];
    __shared__ int idx_s[BM];
    __shared__ int bb_s[BM];
    __shared__ int cnt_s[BM];
    __shared__ int off_s[BM];
    __shared__ int R_s;
    __shared__ unsigned short rowlist[BM * Lsz];

    const int tid = threadIdx.x;
    const int bid = blockIdx.x;

    // ---- prologue ----
    if (tid < 128) {
        s[OGBQ + tid] = gbq[tid];  s[OPBQ + tid] = pbq[tid];
        s[OGV + tid]  = gv[tid];   s[OPV + tid]  = pv[tid];
    }
    for (int i = tid; i < BM * Hsz; i += NT) {
        int m = i >> 7, j = i & 127;
        int bb = min(bid * BM + m, Bsz - 1);
        s[OXH + m * 128 + j] = h0[bb * Hsz + j];
        s[OC  + m * 128 + j] = c0[bb * Hsz + j];
    }
    if (tid < BM) {
        mask_s[tid] = 0ull; idx_s[tid] = 0;
        bb_s[tid] = min(bid * BM + tid, Bsz - 1);
    }
    for (int i = tid; i < BM * Lsz; i += NT) {
        int m = i >> 6, l = i & 63;
        int b = bid * BM + m;
        if (b < Bsz) out[(size_t)b * Lsz + l] = (l == 0) ? 1.0f : 0.0f;
    }
    __syncthreads();

    const int warp = tid >> 5, lane = tid & 31;
    const int grp = lane >> 3, lk = lane & 7;
    const int o128 = tid & 127;
    const int kq = tid >> 7;            // 0..3 (qg/qp split-K slice)
    const int mh = tid >> 8;            // 0..1 (phase A m-group)
    const int o2 = tid & 255;           // phase A output pair {o2, o2+256}
    const int pm0 = mh ? 4 : 0;         // phase A m start
    const int pmN = mh ? 3 : 4;         // phase A m count

    // hoisted attention vectors
    float4 gvr[4], pvr[4];
    #pragma unroll
    for (int j = 0; j < 4; j++) {
        gvr[j] = *reinterpret_cast<const float4*>(&s[OGV + (((j << 3) + lk) << 2)]);
        pvr[j] = *reinterpret_cast<const float4*>(&s[OPV + (((j << 3) + lk) << 2)]);
    }

    for (int step = 0; step < NSTEPS; step++) {
        // ---- preload P rows for phase B ----
        float pA0[2], pA1[2], pA2[2], pA3[2];
        #pragma unroll
        for (int it = 0; it < 2; it++) {
            int i = tid + it * NT;
            if (i < BM * Hsz) {
                int m = i >> 7, j = i & 127;
                const float* pr = (step == 0)
                    ? (d_P0 + (size_t)bb_s[m] * 512)
                    : (d_P + (((size_t)bb_s[m] << 6) + idx_s[m]) * 512);
                pA0[it] = pr[j];       pA1[it] = pr[128 + j];
                pA2[it] = pr[256 + j]; pA3[it] = pr[384 + j];
            }
        }

        // ---- mask update ----
        if (tid < BM) {
            unsigned long long mk = mask_s[tid] | (1ull << idx_s[tid]);
            if (idx_s[tid] != 0) mk &= ~1ull;
            mask_s[tid] = mk;
            cnt_s[tid] = 64 - __popcll(mk);
        }

        // ---- phase A: Whh·h, thread (mh, o2) -> outputs {o2, o2+256} ----
        {
            unsigned long long acc0[4], acc1[4];
            #pragma unroll
            for (int m = 0; m < 4; m++) {
                acc0[m] = pack2(0.f, 0.f);
                acc1[m] = pack2(0.f, 0.f);
            }
            #pragma unroll 4
            for (int kk = 0; kk < 32; kk++) {
                const ulonglong2 wa = *reinterpret_cast<const ulonglong2*>(
                    &d_wt4[((32 + kk) << 9) + o2]);
                const ulonglong2 wb = *reinterpret_cast<const ulonglong2*>(
                    &d_wt4[((32 + kk) << 9) + o2 + 256]);
                #pragma unroll
                for (int m = 0; m < 4; m++) {
                    if (m < pmN) {
                        const ulonglong2 x2 = *reinterpret_cast<const ulonglong2*>(
                            &s[OXH + (pm0 + m) * 128 + (kk << 2)]);
                        FMA2(acc0[m], wa.x, x2.x, acc0[m]);
                        FMA2(acc0[m], wa.y, x2.y, acc0[m]);
                        FMA2(acc1[m], wb.x, x2.x, acc1[m]);
                        FMA2(acc1[m], wb.y, x2.y, acc1[m]);
                    }
                }
            }
            #pragma unroll
            for (int m = 0; m < 4; m++) {
                if (m < pmN) {
                    s[OG + (pm0 + m) * 512 + o2]       = hsum2(acc0[m]);
                    s[OG + (pm0 + m) * 512 + o2 + 256] = hsum2(acc1[m]);
                }
            }
        }
        __syncthreads();

        // ---- phase B: gates + P; LSTM pointwise; rowlist ----
        #pragma unroll
        for (int it = 0; it < 2; it++) {
            int i = tid + it * NT;
            if (i < BM * Hsz) {
                int m = i >> 7, j = i & 127;
                float ig = fsigm(s[OG + m * 512 + j]       + pA0[it]);
                float fg = fsigm(s[OG + m * 512 + 128 + j] + pA1[it]);
                float gg = ftanh(s[OG + m * 512 + 256 + j] + pA2[it]);
                float og = fsigm(s[OG + m * 512 + 384 + j] + pA3[it]);
                float cn = fg * s[OC + m * 128 + j] + ig * gg;
                s[OC + m * 128 + j] = cn;
                s[OXH + m * 128 + j] = og * ftanh(cn);
            }
        }
        if (tid < BM) {
            int off = 0;
            for (int j = 0; j < tid; j++) off += cnt_s[j];
            off_s[tid] = off;
            unsigned long long unm = ~mask_s[tid];
            int k = 0;
            while (unm) {
                int l = __ffsll((long long)unm) - 1;
                rowlist[off + k] = (unsigned short)((tid << 6) | l);
                k++;
                unm &= unm - 1;
            }
        }
        if (tid == 0) {
            int R = 0;
            #pragma unroll
            for (int j = 0; j < BM; j++) R += cnt_s[j];
            R_s = R;
        }
        __syncthreads();

        const int Rv = R_s;
        const int nIter = (Rv + 63) >> 6;   // 16 warps x 4 groups = 64 rows/sweep

        // ---- terminal state: burst uniform 1/64 + exit ----
        if (Rv == 0) {
            const float u = 0.015625f;
            for (int st = step + 1; st <= NSTEPS; st++) {
                float* orow = out + (size_t)st * Bsz * Lsz;
                for (int i = tid; i < BM * Lsz; i += NT) {
                    int m = i >> 6;
                    int b = bid * BM + m;
                    if (b < Bsz) orow[(size_t)b * Lsz + (i & 63)] = u;
                }
            }
            return;
        }

        // ---- qg partials: thread (kq, o128) does 7 m over 8 k4; Wq from global ----
        {
            unsigned long long acc[BM];
            #pragma unroll
            for (int j = 0; j < BM; j++) acc[j] = pack2(0.f, 0.f);
            #pragma unroll
            for (int kk = 0; kk < 8; kk++) {
                const int k4 = (kq << 3) + kk;
                ulonglong2 w2 = *reinterpret_cast<const ulonglong2*>(
                    &d_wq4[(k4 << 7) + o128]);
                #pragma unroll
                for (int j = 0; j < BM; j++) {
                    ulonglong2 h2 = *reinterpret_cast<const ulonglong2*>(
                        &s[OXH + j * 128 + (k4 << 2)]);
                    FMA2(acc[j], w2.x, h2.x, acc[j]);
                    FMA2(acc[j], w2.y, h2.y, acc[j]);
                }
            }
            #pragma unroll
            for (int j = 0; j < BM; j++)
                s[OG + ((kq * BM + j) << 7) + o128] = hsum2(acc[j]);
        }
        __syncthreads();

        // ---- qg reduce (strided: BM*128 = 896 > NT) ----
        for (int i = tid; i < BM * 128; i += NT) {
            int m = i >> 7, o = i & 127;
            float q = ((s[OG + ((m) << 7) + o]           + s[OG + ((BM + m) << 7) + o])
                     + (s[OG + ((2 * BM + m) << 7) + o]  + s[OG + ((3 * BM + m) << 7) + o]))
                     + s[OGBQ + o];
            s[OQ + (m << 7) + o] = q;
        }
        __syncthreads();

        // ---- ug: only unmasked rows ----
        for (int k = 0; k < nIter; k++) {
            int r = warp * 4 + grp + (k << 6);
            bool valid = (r < Rv);
            int e = rowlist[valid ? r : 0];
            int m = e >> 6, l = e & 63;
            const float4* e4 = reinterpret_cast<const float4*>(
                d_eg + ((size_t)bb_s[m] * Lsz + l) * Hsz);
            float acc = 0.f;
            #pragma unroll
            for (int j = 0; j < 4; j++) {
                int k4 = (j << 3) + lk;
                float4 ev = e4[k4];
                float4 q = *reinterpret_cast<const float4*>(&s[OQ + m * 128 + (k4 << 2)]);
                float4 g = gvr[j];
                acc += g.x * ftanh(q.x + ev.x) + g.y * ftanh(q.y + ev.y)
                     + g.z * ftanh(q.z + ev.z) + g.w * ftanh(q.w + ev.w);
            }
            acc += __shfl_xor_sync(0xffffffffu, acc, 1);
            acc += __shfl_xor_sync(0xffffffffu, acc, 2);
            acc += __shfl_xor_sync(0xffffffffu, acc, 4);
            if (valid && lk == 0) s[OU + (m << 6) + l] = acc;
        }
        __syncthreads();

        // ---- glimpse softmax (masked) ----
        if (warp < BM) {
            int m = warp;
            unsigned long long mk = mask_s[m];
            float v0 = ((mk >> lane) & 1ull)        ? NEGV : s[OU + m * 64 + lane];
            float v1 = ((mk >> (lane + 32)) & 1ull) ? NEGV : s[OU + m * 64 + 32 + lane];
            float mx = fmaxf(v0, v1);
            for (int off = 16; off; off >>= 1)
                mx = fmaxf(mx, __shfl_xor_sync(0xffffffffu, mx, off));
            float e0 = __expf(v0 - mx), e1 = __expf(v1 - mx);
            float sum = e0 + e1;
            for (int off = 16; off; off >>= 1)
                sum += __shfl_xor_sync(0xffffffffu, sum, off);
            float inv = __fdividef(1.f, sum);
            s[OS + m * 64 + lane]      = e0 * inv;
            s[OS + m * 64 + 32 + lane] = e1 * inv;
        }
        __syncthreads();

        // ---- g_l[m][h] = sum_l e_g[b][l][h] * sm[m][l] (skip sm==0) ----
        {
            const int mg4 = tid >> 7;
            for (int m = mg4; m < BM; m += 4) {
                const float* eg = d_eg + ((size_t)bb_s[m] * Lsz) * Hsz + o128;
                float acc = 0.f;
                int off = off_s[m], cn = cnt_s[m];
                for (int j = 0; j < cn; j++) {
                    int l = rowlist[off + j] & 63;
                    acc += eg[(size_t)l * Hsz] * s[OS + m * 64 + l];
                }
                s[OGL + m * 128 + o128] = acc;
            }
        }
        __syncthreads();

        // ---- qp partials ----
        {
            unsigned long long acc[BM];
            #pragma unroll
            for (int j = 0; j < BM; j++) acc[j] = pack2(0.f, 0.f);
            #pragma unroll
            for (int kk = 0; kk < 8; kk++) {
                const int k4 = (kq << 3) + kk;
                ulonglong2 w2 = *reinterpret_cast<const ulonglong2*>(
                    &d_wq4[4096 + (k4 << 7) + o128]);
                #pragma unroll
                for (int j = 0; j < BM; j++) {
                    ulonglong2 g2 = *reinterpret_cast<const ulonglong2*>(
                        &s[OGL + j * 128 + (k4 << 2)]);
                    FMA2(acc[j], w2.x, g2.x, acc[j]);
                    FMA2(acc[j], w2.y, g2.y, acc[j]);
                }
            }
            #pragma unroll
            for (int j = 0; j < BM; j++)
                s[OG + ((kq * BM + j) << 7) + o128] = hsum2(acc[j]);
        }
        __syncthreads();

        // ---- qp reduce (strided: BM*128 = 896 > NT) ----
        for (int i = tid; i < BM * 128; i += NT) {
            int m = i >> 7, o = i & 127;
            float q = ((s[OG + ((m) << 7) + o]           + s[OG + ((BM + m) << 7) + o])
                     + (s[OG + ((2 * BM + m) << 7) + o]  + s[OG + ((3 * BM + m) << 7) + o]))
                     + s[OPBQ + o];
            s[OQ + (m << 7) + o] = q;
        }
        __syncthreads();

        // ---- up: only unmasked rows ----
        for (int k = 0; k < nIter; k++) {
            int r = warp * 4 + grp + (k << 6);
            bool valid = (r < Rv);
            int e = rowlist[valid ? r : 0];
            int m = e >> 6, l = e & 63;
            const float4* e4 = reinterpret_cast<const float4*>(
                d_ep + ((size_t)bb_s[m] * Lsz + l) * Hsz);
            float acc = 0.f;
            #pragma unroll
            for (int j = 0; j < 4; j++) {
                int k4 = (j << 3) + lk;
                float4 ev = e4[k4];
                float4 q = *reinterpret_cast<const float4*>(&s[OQ + m * 128 + (k4 << 2)]);
                float4 p = pvr[j];
                acc += p.x * ftanh(q.x + ev.x) + p.y * ftanh(q.y + ev.y)
                     + p.z * ftanh(q.z + ev.z) + p.w * ftanh(q.w + ev.w);
            }
            acc += __shfl_xor_sync(0xffffffffu, acc, 1);
            acc += __shfl_xor_sync(0xffffffffu, acc, 2);
            acc += __shfl_xor_sync(0xffffffffu, acc, 4);
            if (valid && lk == 0) s[OU + (m << 6) + l] = acc;
        }
        __syncthreads();

        // ---- pointer: 10*tanh, mask, softmax, argmax, write probs ----
        if (warp < BM) {
            int m = warp;
            unsigned long long mk = mask_s[m];
            float r0 = 10.f * tanhf(s[OU + m * 64 + lane]);
            float r1 = 10.f * tanhf(s[OU + m * 64 + 32 + lane]);
            float v0 = ((mk >> lane) & 1ull)        ? NEGV : r0;
            float v1 = ((mk >> (lane + 32)) & 1ull) ? NEGV : r1;
            float mv2; int mi;
            if (v0 >= v1) { mv2 = v0; mi = lane; } else { mv2 = v1; mi = lane + 32; }
            for (int off = 16; off; off >>= 1) {
                float ov = __shfl_xor_sync(0xffffffffu, mv2, off);
                int   oi = __shfl_xor_sync(0xffffffffu, mi, off);
                if (ov > mv2 || (ov == mv2 && oi < mi)) { mv2 = ov; mi = oi; }
            }
            float e0 = __expf(v0 - mv2), e1 = __expf(v1 - mv2);
            float sum = e0 + e1;
            for (int off = 16; off; off >>= 1)
                sum += __shfl_xor_sync(0xffffffffu, sum, off);
            float inv = __fdividef(1.f, sum);
            int b = bid * BM + m;
            if (b < Bsz) {
                float* op = out + ((size_t)(step + 1) * Bsz + b) * Lsz;
                op[lane]      = e0 * inv;
                op[lane + 32] = e1 * inv;
            }
            if (lane == 0) idx_s[m] = mi;
        }
        __syncthreads();
    }
}

extern "C" void kernel_launch(void* const* d_in, const int* in_sizes, int n_in,
                              void* d_out, int out_size)
{
    const float* dec   = (const float*)d_in[0];
    const float* emb   = (const float*)d_in[1];
    const float* ctx   = (const float*)d_in[2];
    const float* h0    = (const float*)d_in[3];
    const float* c0    = (const float*)d_in[4];
    const float* Wih   = (const float*)d_in[5];
    const float* Whh   = (const float*)d_in[6];
    const float* bih   = (const float*)d_in[7];
    const float* bhh   = (const float*)d_in[8];
    const float* gWq   = (const float*)d_in[9];
    const float* gbq   = (const float*)d_in[10];
    const float* gWref = (const float*)d_in[11];
    const float* gbref = (const float*)d_in[12];
    const float* gv    = (const float*)d_in[13];
    const float* pWq   = (const float*)d_in[14];
    const float* pbq   = (const float*)d_in[15];
    const float* pWref = (const float*)d_in[16];
    const float* pbref = (const float*)d_in[17];
    const float* pv    = (const float*)d_in[18];
    float* out = (float*)d_out;

    cudaFuncSetAttribute(ptrnet_main, cudaFuncAttributeMaxDynamicSharedMemorySize,
                         SMEM_FLOATS * 4);

    ptrnet_prew<<<80, 512>>>(Wih, Whh, gWq, pWq);
    ptrnet_preP<<<Bsz, 512>>>(emb, dec, bih, bhh);
    ptrnet_pre<<<Bsz, 128>>>(ctx, gWref, gbref, pWref, pbref);
    ptrnet_main<<<GRID, NT, SMEM_FLOATS * 4>>>(h0, c0, gbq, pbq, gv, pv, out);
}